// round 6
// baseline (speedup 1.0000x reference)
#include <cuda_runtime.h>

// Problem constants: B=2, N=8192, T=32, C=64, K=16, NUM_BASES=4
#define Bv 2
#define Nv 8192
#define Tv 32
#define Cv 64
#define Kv 16
#define NB 4
#define TC4 (Tv * Cv / 4)   // 512 float4 per (b,n) row

// out[b,n,t,c] = tanh( sum_k z[b, nbr[n,k], t, c] * w[c,n,k] )
// w[c,n,k] = adj[n,k] * sum_base cc[c,base] * bw[base,n,k]
//
// 128 threads/CTA. Thread = (c4 = tid&15, th = tid>>4, 0..7), owns 4 output
// slots s = c4 + 16*(th + 8j), j=0..3. One weight float4 per k serves 4
// outputs. Live registers ~60 -> 8 CTAs/SM (32 warps, 50% occ) to drive the
// L2 request stream; gather wavefronts stay at the compulsory 1024/CTA.
__global__ __launch_bounds__(128, 8)
void geodcd_kernel(const float4* __restrict__ z4,
                   const int*    __restrict__ nbr,
                   const float*  __restrict__ adj,
                   const float*  __restrict__ bw,
                   const float*  __restrict__ cc,
                   float4*       __restrict__ out4)
{
    const int n   = blockIdx.x;
    const int b   = blockIdx.y;
    const int tid = threadIdx.x;   // 128 threads
    const int c4  = tid & 15;
    const int th  = tid >> 4;      // 0..7

    __shared__ float ws[Kv * Cv];     // [k][c] effective edge weights (4 KB)
    __shared__ float scc[NB * Cv];    // transposed channel coeffs [base][c]
    __shared__ float sbw[NB * Kv];    // basis weights for this n [base][k]
    __shared__ float sadj[Kv];

    // ---- cooperative, coalesced staging ----
    // cc is [C][NB] = 64 rows of float4; threads 0..63 load row tid (coalesced).
    if (tid < Cv) {
        const float4 ccv = reinterpret_cast<const float4*>(cc)[tid];
        scc[0 * Cv + tid] = ccv.x;   // transpose to [base][c]
        scc[1 * Cv + tid] = ccv.y;
        scc[2 * Cv + tid] = ccv.z;
        scc[3 * Cv + tid] = ccv.w;
    }
    // bw[base][n][k]: 64 scalars for this n.
    if (tid < NB * Kv)
        sbw[tid] = bw[(size_t)(tid >> 4) * (Nv * Kv) + n * Kv + (tid & 15)];
    if (tid < Kv) sadj[tid] = adj[n * Kv + tid];
    // Neighbor index in lane register: lane l holds nbr[n][l&15] (per-warp).
    const int rnbr = nbr[n * Kv + c4];
    __syncthreads();

    // ---- weight build: threads 0..63 compute w[k][4*c4 .. 4*c4+3], 4 k's each
    if (tid < 64) {
        const int bc4 = tid & 15;
        const int bth = tid >> 4;   // 0..3
        const float4 cb0 = reinterpret_cast<const float4*>(scc + 0 * Cv)[bc4];
        const float4 cb1 = reinterpret_cast<const float4*>(scc + 1 * Cv)[bc4];
        const float4 cb2 = reinterpret_cast<const float4*>(scc + 2 * Cv)[bc4];
        const float4 cb3 = reinterpret_cast<const float4*>(scc + 3 * Cv)[bc4];
        #pragma unroll
        for (int p = 0; p < 4; ++p) {
            const int k = bth + 4 * p;
            const float a  = sadj[k];
            const float b0 = sbw[0 * Kv + k];
            const float b1 = sbw[1 * Kv + k];
            const float b2 = sbw[2 * Kv + k];
            const float b3 = sbw[3 * Kv + k];
            float4 w;
            w.x = a * (cb0.x * b0 + cb1.x * b1 + cb2.x * b2 + cb3.x * b3);
            w.y = a * (cb0.y * b0 + cb1.y * b1 + cb2.y * b2 + cb3.y * b3);
            w.z = a * (cb0.z * b0 + cb1.z * b1 + cb2.z * b2 + cb3.z * b3);
            w.w = a * (cb0.w * b0 + cb1.w * b1 + cb2.w * b2 + cb3.w * b3);
            reinterpret_cast<float4*>(ws)[k * (Cv / 4) + bc4] = w;
        }
    }
    __syncthreads();

    // ---- gather + accumulate ----
    const float4* zb = z4 + (size_t)b * Nv * TC4;
    float4* op = out4 + ((size_t)b * Nv + n) * TC4;
    const int sbase = c4 + 16 * th;   // slot for j=0; j-th slot = sbase + 128*j

    float4 acc0 = make_float4(0.f, 0.f, 0.f, 0.f);
    float4 acc1 = make_float4(0.f, 0.f, 0.f, 0.f);
    float4 acc2 = make_float4(0.f, 0.f, 0.f, 0.f);
    float4 acc3 = make_float4(0.f, 0.f, 0.f, 0.f);

    #pragma unroll
    for (int k = 0; k < Kv; ++k) {
        const int nb = __shfl_sync(0xffffffffu, rnbr, k);   // lane k&15 holds nbr k
        const float4 w = reinterpret_cast<const float4*>(ws)[k * (Cv / 4) + c4];
        const float4* row = zb + (size_t)nb * TC4 + sbase;
        const float4 z0 = __ldg(row);
        const float4 z1 = __ldg(row + 128);
        const float4 z2 = __ldg(row + 256);
        const float4 z3 = __ldg(row + 384);
        acc0.x = fmaf(z0.x, w.x, acc0.x);
        acc0.y = fmaf(z0.y, w.y, acc0.y);
        acc0.z = fmaf(z0.z, w.z, acc0.z);
        acc0.w = fmaf(z0.w, w.w, acc0.w);
        acc1.x = fmaf(z1.x, w.x, acc1.x);
        acc1.y = fmaf(z1.y, w.y, acc1.y);
        acc1.z = fmaf(z1.z, w.z, acc1.z);
        acc1.w = fmaf(z1.w, w.w, acc1.w);
        acc2.x = fmaf(z2.x, w.x, acc2.x);
        acc2.y = fmaf(z2.y, w.y, acc2.y);
        acc2.z = fmaf(z2.z, w.z, acc2.z);
        acc2.w = fmaf(z2.w, w.w, acc2.w);
        acc3.x = fmaf(z3.x, w.x, acc3.x);
        acc3.y = fmaf(z3.y, w.y, acc3.y);
        acc3.z = fmaf(z3.z, w.z, acc3.z);
        acc3.w = fmaf(z3.w, w.w, acc3.w);
    }

    float4 r0, r1, r2, r3;
    r0.x = tanhf(acc0.x); r0.y = tanhf(acc0.y); r0.z = tanhf(acc0.z); r0.w = tanhf(acc0.w);
    r1.x = tanhf(acc1.x); r1.y = tanhf(acc1.y); r1.z = tanhf(acc1.z); r1.w = tanhf(acc1.w);
    r2.x = tanhf(acc2.x); r2.y = tanhf(acc2.y); r2.z = tanhf(acc2.z); r2.w = tanhf(acc2.w);
    r3.x = tanhf(acc3.x); r3.y = tanhf(acc3.y); r3.z = tanhf(acc3.z); r3.w = tanhf(acc3.w);
    op[sbase]       = r0;
    op[sbase + 128] = r1;
    op[sbase + 256] = r2;
    op[sbase + 384] = r3;
}

extern "C" void kernel_launch(void* const* d_in, const int* in_sizes, int n_in,
                              void* d_out, int out_size) {
    // metadata order: z, neighbor_indices, adjacency, basis_weights, channel_coeffs
    const float4* z4  = (const float4*)d_in[0];
    const int*    nbr = (const int*)   d_in[1];
    const float*  adj = (const float*) d_in[2];
    const float*  bw  = (const float*) d_in[3];
    const float*  cc  = (const float*) d_in[4];
    float4*       o4  = (float4*)      d_out;

    dim3 grid(Nv, Bv);   // b-major wave ordering keeps one batch's z L2-resident
    geodcd_kernel<<<grid, 128>>>(z4, nbr, adj, bw, cc, o4);
}

// round 7
// speedup vs baseline: 1.0173x; 1.0173x over previous
#include <cuda_runtime.h>

// Problem constants: B=2, N=8192, T=32, C=64, K=16, NUM_BASES=4
#define Bv 2
#define Nv 8192
#define Tv 32
#define Cv 64
#define Kv 16
#define NB 4
#define TC4 (Tv * Cv / 4)   // 512 float4 per (b,n) row

// out[b,n,t,c] = tanh( sum_k z[b, nbr[n,k], t, c] * w[c,n,k] )
// w[c,n,k] = adj[n,k] * sum_base cc[c,base] * bw[base,n,k]
//
// 64 threads/CTA, thread = (c4 = tid&15, th = tid>>4), owns 8 output slots.
// NEW in R7: every CTA processes its 16 neighbors in ASCENDING index order
// (16-lane bitonic sort via shfl.xor, key = (nbr<<4)|k). All CTAs in a wave
// then sweep the z array in near-lockstep -> z reuse clusters in time, stays
// L2-resident, DRAM re-fetch drops. Outputs stored with __stcs so the output
// stream doesn't evict z from L2.
__global__ __launch_bounds__(64, 10)
void geodcd_kernel(const float4* __restrict__ z4,
                   const int*    __restrict__ nbr,
                   const float*  __restrict__ adj,
                   const float*  __restrict__ bw,
                   const float*  __restrict__ cc,
                   float4*       __restrict__ out4)
{
    const int n   = blockIdx.x;
    const int b   = blockIdx.y;
    const int tid = threadIdx.x;   // 64 threads
    const int c4  = tid & 15;
    const int th  = tid >> 4;      // 0..3

    __shared__ float ws[Kv * Cv];     // [k][c] effective edge weights (4 KB)
    __shared__ float scc[NB * Cv];    // transposed channel coeffs [base][c]
    __shared__ float sbw[NB * Kv];    // basis weights for this n [base][k]
    __shared__ float sadj[Kv];

    // ---- cooperative, coalesced staging ----
    {
        const float4 ccv = reinterpret_cast<const float4*>(cc)[tid];
        scc[0 * Cv + tid] = ccv.x;   // transpose to [base][c]
        scc[1 * Cv + tid] = ccv.y;
        scc[2 * Cv + tid] = ccv.z;
        scc[3 * Cv + tid] = ccv.w;
    }
    sbw[tid] = bw[(size_t)th * (Nv * Kv) + n * Kv + c4];  // [base=th][k=c4]
    if (tid < Kv) sadj[tid] = adj[n * Kv + tid];

    // Neighbor index into lane register, packed with its k: (nbr<<4)|k.
    unsigned pk = ((unsigned)nbr[n * Kv + c4] << 4) | (unsigned)c4;

    // 16-element bitonic sort across lanes (lane&15); lanes 16-31 mirror
    // lanes 0-15 so both half-warps hold identical sorted sequences.
    #pragma unroll
    for (int size = 2; size <= 16; size <<= 1) {
        #pragma unroll
        for (int stride = size >> 1; stride > 0; stride >>= 1) {
            const unsigned q = __shfl_xor_sync(0xffffffffu, pk, stride);
            const bool dirUp = ((c4 & size) == 0);
            const bool lower = ((c4 & stride) == 0);
            pk = ((lower == dirUp) ? umin(pk, q) : umax(pk, q));
        }
    }
    __syncthreads();

    // ---- weight build: thread computes w[k][4*c4 .. 4*c4+3] for 4 k's ----
    {
        const float4 cb0 = reinterpret_cast<const float4*>(scc + 0 * Cv)[c4];
        const float4 cb1 = reinterpret_cast<const float4*>(scc + 1 * Cv)[c4];
        const float4 cb2 = reinterpret_cast<const float4*>(scc + 2 * Cv)[c4];
        const float4 cb3 = reinterpret_cast<const float4*>(scc + 3 * Cv)[c4];
        #pragma unroll
        for (int p = 0; p < 4; ++p) {
            const int k = th + 4 * p;
            const float a  = sadj[k];
            const float b0 = sbw[0 * Kv + k];
            const float b1 = sbw[1 * Kv + k];
            const float b2 = sbw[2 * Kv + k];
            const float b3 = sbw[3 * Kv + k];
            float4 w;
            w.x = a * (cb0.x * b0 + cb1.x * b1 + cb2.x * b2 + cb3.x * b3);
            w.y = a * (cb0.y * b0 + cb1.y * b1 + cb2.y * b2 + cb3.y * b3);
            w.z = a * (cb0.z * b0 + cb1.z * b1 + cb2.z * b2 + cb3.z * b3);
            w.w = a * (cb0.w * b0 + cb1.w * b1 + cb2.w * b2 + cb3.w * b3);
            reinterpret_cast<float4*>(ws)[k * (Cv / 4) + c4] = w;
        }
    }
    __syncthreads();

    // ---- gather + accumulate, neighbors in ascending index order ----
    const float4* zb = z4 + (size_t)b * Nv * TC4;
    float4* op = out4 + ((size_t)b * Nv + n) * TC4;
    const int sbase = c4 + 16 * th;   // slot for j=0; j-th slot = sbase + 64*j

    float4 acc[8];
    #pragma unroll
    for (int j = 0; j < 8; ++j) acc[j] = make_float4(0.f, 0.f, 0.f, 0.f);

    #pragma unroll
    for (int i = 0; i < Kv; ++i) {
        const unsigned p  = __shfl_sync(0xffffffffu, pk, i);  // sorted elem i
        const int nb = (int)(p >> 4);
        const int k  = (int)(p & 15u);
        const float4 w = reinterpret_cast<const float4*>(ws)[k * (Cv / 4) + c4];
        const float4* row = zb + (size_t)nb * TC4 + sbase;
        #pragma unroll
        for (int j = 0; j < 8; ++j) {
            const float4 zv = __ldg(row + 64 * j);
            acc[j].x = fmaf(zv.x, w.x, acc[j].x);
            acc[j].y = fmaf(zv.y, w.y, acc[j].y);
            acc[j].z = fmaf(zv.z, w.z, acc[j].z);
            acc[j].w = fmaf(zv.w, w.w, acc[j].w);
        }
    }

    #pragma unroll
    for (int j = 0; j < 8; ++j) {
        float4 r;
        r.x = tanhf(acc[j].x);
        r.y = tanhf(acc[j].y);
        r.z = tanhf(acc[j].z);
        r.w = tanhf(acc[j].w);
        __stcs(op + sbase + 64 * j, r);   // streaming store: don't pollute L2
    }
}

extern "C" void kernel_launch(void* const* d_in, const int* in_sizes, int n_in,
                              void* d_out, int out_size) {
    // metadata order: z, neighbor_indices, adjacency, basis_weights, channel_coeffs
    const float4* z4  = (const float4*)d_in[0];
    const int*    nbr = (const int*)   d_in[1];
    const float*  adj = (const float*) d_in[2];
    const float*  bw  = (const float*) d_in[3];
    const float*  cc  = (const float*) d_in[4];
    float4*       o4  = (float4*)      d_out;

    dim3 grid(Nv, Bv);   // b-major wave ordering keeps one batch's z L2-resident
    geodcd_kernel<<<grid, 64>>>(z4, nbr, adj, bw, cc, o4);
}